// round 4
// baseline (speedup 1.0000x reference)
#include <cuda_runtime.h>
#include <cuda_bf16.h>
#include <cstdint>

// Problem constants (static per reference): V voxels, 40 labels (1..40).
static constexpr int X = 256, Y = 256, Z = 48;
static constexpr int V = X * Y * Z;          // 3,145,728 voxels
static constexpr int NLAB = 40;              // channels
static constexpr int V4 = V / 4;             // 786,432 float4 groups per channel plane

__global__ __launch_bounds__(256)
void onehot_kernel(const float* __restrict__ mask, float* __restrict__ out) {
    const size_t idx = (size_t)blockIdx.x * blockDim.x + threadIdx.x; // one float4 of voxels
    // Load 4 labels (small non-negative ints stored as fp32).
    const float4 m = __ldg(reinterpret_cast<const float4*>(mask) + idx);
    const int l0 = (int)m.x;
    const int l1 = (int)m.y;
    const int l2 = (int)m.z;
    const int l3 = (int)m.w;

    float4* o = reinterpret_cast<float4*>(out) + idx;
    #pragma unroll
    for (int c = 1; c <= NLAB; ++c) {
        float4 r;
        r.x = (l0 == c) ? 1.0f : 0.0f;
        r.y = (l1 == c) ? 1.0f : 0.0f;
        r.z = (l2 == c) ? 1.0f : 0.0f;
        r.w = (l3 == c) ? 1.0f : 0.0f;
        // Streaming store: output (503 MB) is 4x L2 capacity — evict-first.
        __stcs(o, r);
        o += (size_t)V4;   // next channel plane
    }
}

extern "C" void kernel_launch(void* const* d_in, const int* in_sizes, int n_in,
                              void* d_out, int out_size) {
    const float* mask = (const float*)d_in[0];
    float* out = (float*)d_out;
    // V4 threads, 256/block -> 3072 blocks (full chip, multiple waves of CTAs/SM)
    onehot_kernel<<<V4 / 256, 256>>>(mask, out);
}